// round 1
// baseline (speedup 1.0000x reference)
#include <cuda_runtime.h>

#define NB 8      // batch
#define NP 3249   // grid points
#define NS 128    // axon segments
#define NE 60     // electrodes
#define WARPS_PER_BLOCK 4
#define THREADS (WARPS_PER_BLOCK * 32)

// One warp per grid point p.
// lane owns s-rows {lane, lane+32, lane+64, lane+96}.
// acc[r][b] accumulates ipa[b, p, s_r] over all 60 electrodes.
// amp (8x60 floats) staged in shared memory, read as broadcast float4.
__global__ __launch_bounds__(THREADS)
void axon_map_kernel(const float* __restrict__ amp,
                     const float* __restrict__ pexp,
                     float* __restrict__ out) {
    __shared__ float amp_s[NB * NE];

    const int tid = threadIdx.x;
    for (int i = tid; i < NB * NE; i += THREADS) amp_s[i] = amp[i];
    __syncthreads();

    const int warp = tid >> 5;
    const int lane = tid & 31;
    const int p = blockIdx.x * WARPS_PER_BLOCK + warp;
    if (p >= NP) return;

    const float* base = pexp + (size_t)p * (NS * NE);

    float acc[4][NB];
    #pragma unroll
    for (int r = 0; r < 4; r++) {
        #pragma unroll
        for (int b = 0; b < NB; b++) acc[r][b] = 0.0f;
    }

    // NE = 60 -> 15 float4 chunks along the electrode axis.
    #pragma unroll 3
    for (int j = 0; j < NE / 4; j++) {
        float4 pe[4];
        #pragma unroll
        for (int r = 0; r < 4; r++) {
            const int s = lane + 32 * r;
            // offset in floats: s*60 + 4j  -> 16B aligned (60 % 4 == 0)
            pe[r] = *reinterpret_cast<const float4*>(base + s * NE + 4 * j);
        }
        #pragma unroll
        for (int b = 0; b < NB; b++) {
            const float4 a = *reinterpret_cast<const float4*>(&amp_s[b * NE + 4 * j]);
            #pragma unroll
            for (int r = 0; r < 4; r++) {
                acc[r][b] = fmaf(pe[r].x, a.x, acc[r][b]);
                acc[r][b] = fmaf(pe[r].y, a.y, acc[r][b]);
                acc[r][b] = fmaf(pe[r].z, a.z, acc[r][b]);
                acc[r][b] = fmaf(pe[r].w, a.w, acc[r][b]);
            }
        }
    }

    // Per-batch: pick the segment with max |intensity| (local over 4 rows,
    // then warp shuffle reduction over 32 lanes). Write its signed value.
    #pragma unroll
    for (int b = 0; b < NB; b++) {
        float bv = acc[0][b];
        float ba = fabsf(bv);
        #pragma unroll
        for (int r = 1; r < 4; r++) {
            const float a = fabsf(acc[r][b]);
            if (a > ba) { ba = a; bv = acc[r][b]; }
        }
        #pragma unroll
        for (int off = 16; off > 0; off >>= 1) {
            const float oa = __shfl_xor_sync(0xffffffffu, ba, off);
            const float ov = __shfl_xor_sync(0xffffffffu, bv, off);
            if (oa > ba) { ba = oa; bv = ov; }
        }
        if (lane == 0) {
            // threshold |v| > 0 is identity for nonzero v; v==0 maps to 0 anyway
            out[b * NP + p] = bv;
        }
    }
}

extern "C" void kernel_launch(void* const* d_in, const int* in_sizes, int n_in,
                              void* d_out, int out_size) {
    (void)n_in; (void)out_size;
    const float* a0 = (const float*)d_in[0];
    const float* a1 = (const float*)d_in[1];
    // amp has B*E = 480 elements; p_exp has P*S*E*1 = 24,952,320.
    const float* amp  = a0;
    const float* pexp = a1;
    if (in_sizes[0] != NB * NE) { amp = a1; pexp = a0; }

    const int grid = (NP + WARPS_PER_BLOCK - 1) / WARPS_PER_BLOCK;
    axon_map_kernel<<<grid, THREADS>>>(amp, pexp, (float*)d_out);
}

// round 2
// speedup vs baseline: 1.3678x; 1.3678x over previous
#include <cuda_runtime.h>

#define NB 8      // batch
#define NP 3249   // grid points
#define NS 128    // axon segments
#define NE 60     // electrodes
#define THREADS 128

// One block per grid point p. Stage the 128x60 fp32 tile in smem via
// coalesced cp.async, then one thread per segment s accumulates all 8
// batches. amp is staged transposed [e][b] so batches vectorize as float4.
__global__ __launch_bounds__(THREADS)
void axon_map_kernel(const float* __restrict__ amp,
                     const float* __restrict__ pexp,
                     float* __restrict__ out) {
    __shared__ float tile[NS * NE];     // 30720 B, coalesced-staged
    __shared__ float ampt[NE * NB];     // amp transposed: [e][b]
    __shared__ float red_a[4][NB];
    __shared__ float red_v[4][NB];

    const int tid = threadIdx.x;
    const int p = blockIdx.x;
    const float* src = pexp + (size_t)p * (NS * NE);

    // Coalesced async stage: 1920 float4s, 15 per thread, all in flight.
    {
        const unsigned smem_base = (unsigned)__cvta_generic_to_shared(tile);
        #pragma unroll
        for (int i = 0; i < (NS * NE / 4) / THREADS; i++) {  // 15
            const int idx = (i * THREADS + tid) * 4;         // float index
            asm volatile("cp.async.cg.shared.global [%0], [%1], 16;\n"
                         :: "r"(smem_base + idx * 4), "l"(src + idx));
        }
        asm volatile("cp.async.commit_group;\n" ::: "memory");
    }

    // amp transpose (tiny: 480 elems), overlapped with the cp.async flight.
    for (int i = tid; i < NB * NE; i += THREADS) {
        const int b = i / NE, e = i % NE;
        ampt[e * NB + b] = amp[i];
    }

    asm volatile("cp.async.wait_group 0;\n" ::: "memory");
    __syncthreads();

    // thread tid owns segment s = tid.
    const float* row = tile + tid * NE;   // conflict-free LDS.128 (stride 60 words)
    float acc[NB];
    #pragma unroll
    for (int b = 0; b < NB; b++) acc[b] = 0.0f;

    #pragma unroll
    for (int j = 0; j < NE / 4; j++) {
        const float4 r = *reinterpret_cast<const float4*>(row + 4 * j);
        const float re[4] = {r.x, r.y, r.z, r.w};
        #pragma unroll
        for (int k = 0; k < 4; k++) {
            const int e = 4 * j + k;
            const float4 a0 = *reinterpret_cast<const float4*>(ampt + e * NB);
            const float4 a1 = *reinterpret_cast<const float4*>(ampt + e * NB + 4);
            acc[0] = fmaf(re[k], a0.x, acc[0]);
            acc[1] = fmaf(re[k], a0.y, acc[1]);
            acc[2] = fmaf(re[k], a0.z, acc[2]);
            acc[3] = fmaf(re[k], a0.w, acc[3]);
            acc[4] = fmaf(re[k], a1.x, acc[4]);
            acc[5] = fmaf(re[k], a1.y, acc[5]);
            acc[6] = fmaf(re[k], a1.z, acc[6]);
            acc[7] = fmaf(re[k], a1.w, acc[7]);
        }
    }

    // abs-argmax over the 128 segments: warp shuffle, then cross-warp via smem.
    const int warp = tid >> 5;
    const int lane = tid & 31;
    #pragma unroll
    for (int b = 0; b < NB; b++) {
        float bv = acc[b];
        float ba = fabsf(bv);
        #pragma unroll
        for (int off = 16; off > 0; off >>= 1) {
            const float oa = __shfl_xor_sync(0xffffffffu, ba, off);
            const float ov = __shfl_xor_sync(0xffffffffu, bv, off);
            if (oa > ba) { ba = oa; bv = ov; }
        }
        if (lane == 0) { red_a[warp][b] = ba; red_v[warp][b] = bv; }
    }
    __syncthreads();

    if (tid < NB) {
        float ba = red_a[0][tid];
        float bv = red_v[0][tid];
        #pragma unroll
        for (int w = 1; w < 4; w++) {
            if (red_a[w][tid] > ba) { ba = red_a[w][tid]; bv = red_v[w][tid]; }
        }
        // threshold |v| > 0 is identity here
        out[tid * NP + p] = bv;
    }
}

extern "C" void kernel_launch(void* const* d_in, const int* in_sizes, int n_in,
                              void* d_out, int out_size) {
    (void)n_in; (void)out_size;
    const float* a0 = (const float*)d_in[0];
    const float* a1 = (const float*)d_in[1];
    const float* amp  = a0;
    const float* pexp = a1;
    if (in_sizes[0] != NB * NE) { amp = a1; pexp = a0; }

    axon_map_kernel<<<NP, THREADS>>>(amp, pexp, (float*)d_out);
}

// round 3
// speedup vs baseline: 1.7074x; 1.2483x over previous
#include <cuda_runtime.h>
#include <cstdint>

#define NB 8      // batch
#define NP 3249   // grid points
#define NS 128    // axon segments
#define NE 60     // electrodes
#define THREADS 64
#define TILE_BYTES (NS * NE * 4)   // 30720

__device__ __forceinline__ unsigned long long dup2(float x) {
    unsigned long long r;
    asm("mov.b64 %0, {%1, %1};" : "=l"(r) : "f"(x));
    return r;
}
__device__ __forceinline__ void fma2(unsigned long long& d,
                                     unsigned long long a,
                                     unsigned long long b) {
    asm("fma.rn.f32x2 %0, %1, %2, %0;" : "+l"(d) : "l"(a), "l"(b));
}

// One block (64 threads) per grid point. Tile staged by one cp.async.bulk.
// Thread t owns segments t and t+64; amp transposed [e][b] in smem, read as
// 16B broadcasts feeding packed f32x2 FMAs (batches in pairs).
__global__ __launch_bounds__(THREADS)
void axon_map_kernel(const float* __restrict__ amp,
                     const float* __restrict__ pexp,
                     float* __restrict__ out) {
    __shared__ __align__(128) float tile[NS * NE];
    __shared__ __align__(16) float ampt[NE * NB];   // [e][b]
    __shared__ __align__(8) unsigned long long mbar[1];
    __shared__ float red_a[2][NB];
    __shared__ float red_v[2][NB];

    const int tid = threadIdx.x;
    const int p = blockIdx.x;
    const float* src = pexp + (size_t)p * (NS * NE);

    const uint32_t mbar_addr = (uint32_t)__cvta_generic_to_shared(mbar);
    const uint32_t tile_addr = (uint32_t)__cvta_generic_to_shared(tile);

    if (tid == 0) {
        asm volatile("mbarrier.init.shared.b64 [%0], 1;" :: "r"(mbar_addr) : "memory");
    }
    __syncthreads();
    if (tid == 0) {
        asm volatile("mbarrier.arrive.expect_tx.shared.b64 _, [%0], %1;"
                     :: "r"(mbar_addr), "r"((uint32_t)TILE_BYTES) : "memory");
        asm volatile("cp.async.bulk.shared::cluster.global.mbarrier::complete_tx::bytes "
                     "[%0], [%1], %2, [%3];"
                     :: "r"(tile_addr), "l"(src), "r"((uint32_t)TILE_BYTES), "r"(mbar_addr)
                     : "memory");
    }

    // Stage amp transposed (480 floats) while the bulk copy is in flight.
    for (int i = tid; i < NB * NE; i += THREADS) {
        const int b = i / NE, e = i % NE;
        ampt[e * NB + b] = amp[i];
    }

    // Wait for the bulk copy (parity 0, fresh barrier each launch).
    {
        uint32_t done;
        asm volatile("{\n\t.reg .pred p;\n\t"
                     "mbarrier.try_wait.parity.acquire.cta.shared::cta.b64 p, [%1], %2;\n\t"
                     "selp.b32 %0, 1, 0, p;\n\t}"
                     : "=r"(done) : "r"(mbar_addr), "r"(0u) : "memory");
        while (!done) {
            asm volatile("{\n\t.reg .pred p;\n\t"
                         "mbarrier.try_wait.parity.acquire.cta.shared::cta.b64 p, [%1], %2, 0x989680;\n\t"
                         "selp.b32 %0, 1, 0, p;\n\t}"
                         : "=r"(done) : "r"(mbar_addr), "r"(0u) : "memory");
        }
    }
    __syncthreads();

    const float* row0 = tile + tid * NE;
    const float* row1 = tile + (tid + 64) * NE;

    unsigned long long acc0[4], acc1[4];   // 4 pairs = 8 batches each
    #pragma unroll
    for (int q = 0; q < 4; q++) { acc0[q] = 0ull; acc1[q] = 0ull; }

    #pragma unroll
    for (int j = 0; j < NE / 4; j++) {
        const float4 r0 = *reinterpret_cast<const float4*>(row0 + 4 * j);
        const float4 r1 = *reinterpret_cast<const float4*>(row1 + 4 * j);
        const float re0[4] = {r0.x, r0.y, r0.z, r0.w};
        const float re1[4] = {r1.x, r1.y, r1.z, r1.w};
        #pragma unroll
        for (int k = 0; k < 4; k++) {
            const int e = 4 * j + k;
            const ulonglong2 alo = *reinterpret_cast<const ulonglong2*>(ampt + e * NB);
            const ulonglong2 ahi = *reinterpret_cast<const ulonglong2*>(ampt + e * NB + 4);
            const unsigned long long d0 = dup2(re0[k]);
            fma2(acc0[0], d0, alo.x);
            fma2(acc0[1], d0, alo.y);
            fma2(acc0[2], d0, ahi.x);
            fma2(acc0[3], d0, ahi.y);
            const unsigned long long d1 = dup2(re1[k]);
            fma2(acc1[0], d1, alo.x);
            fma2(acc1[1], d1, alo.y);
            fma2(acc1[2], d1, ahi.x);
            fma2(acc1[3], d1, ahi.y);
        }
    }

    // abs-argmax across the 128 segments per batch.
    const int warp = tid >> 5;
    const int lane = tid & 31;
    #pragma unroll
    for (int b = 0; b < NB; b++) {
        const unsigned long long p0 = acc0[b >> 1];
        const unsigned long long p1 = acc1[b >> 1];
        const float v0 = __uint_as_float((b & 1) ? (uint32_t)(p0 >> 32) : (uint32_t)p0);
        const float v1 = __uint_as_float((b & 1) ? (uint32_t)(p1 >> 32) : (uint32_t)p1);
        float bv = v0, ba = fabsf(v0);
        const float a1 = fabsf(v1);
        if (a1 > ba) { ba = a1; bv = v1; }
        #pragma unroll
        for (int off = 16; off > 0; off >>= 1) {
            const float oa = __shfl_xor_sync(0xffffffffu, ba, off);
            const float ov = __shfl_xor_sync(0xffffffffu, bv, off);
            if (oa > ba) { ba = oa; bv = ov; }
        }
        if (lane == 0) { red_a[warp][b] = ba; red_v[warp][b] = bv; }
    }
    __syncthreads();

    if (tid < NB) {
        float ba = red_a[0][tid];
        float bv = red_v[0][tid];
        if (red_a[1][tid] > ba) { bv = red_v[1][tid]; }
        out[tid * NP + p] = bv;   // threshold |v|>0 is identity
    }
}

extern "C" void kernel_launch(void* const* d_in, const int* in_sizes, int n_in,
                              void* d_out, int out_size) {
    (void)n_in; (void)out_size;
    const float* a0 = (const float*)d_in[0];
    const float* a1 = (const float*)d_in[1];
    const float* amp  = a0;
    const float* pexp = a1;
    if (in_sizes[0] != NB * NE) { amp = a1; pexp = a0; }

    axon_map_kernel<<<NP, THREADS>>>(amp, pexp, (float*)d_out);
}

// round 4
// speedup vs baseline: 1.7289x; 1.0126x over previous
#include <cuda_runtime.h>
#include <cstdint>

#define NB 8      // batch
#define NP 3249   // grid points
#define NS 128    // axon segments
#define NE 60     // electrodes
#define THREADS 128
#define NBLOCKS 148
#define SLOTS 2
#define NSLOTS (NBLOCKS * SLOTS)      // 296
#define STAGES 2
#define TILE_FLOATS (NS * NE)         // 7680
#define TILE_BYTES (TILE_FLOATS * 4)  // 30720

#define SMEM_TILES_FLOATS (SLOTS * STAGES * TILE_FLOATS)
#define SMEM_BYTES (SMEM_TILES_FLOATS * 4 + NE * NB * 4 + SLOTS * STAGES * 8 + SLOTS * 2 * NB * 2 * 4 + 64)

__device__ __forceinline__ unsigned long long dup2(float x) {
    unsigned long long r;
    asm("mov.b64 %0, {%1, %1};" : "=l"(r) : "f"(x));
    return r;
}
__device__ __forceinline__ void fma2(unsigned long long& d,
                                     unsigned long long a,
                                     unsigned long long b) {
    asm("fma.rn.f32x2 %0, %1, %2, %0;" : "+l"(d) : "l"(a), "l"(b));
}

__device__ __forceinline__ void mbar_wait(uint32_t addr, uint32_t parity) {
    uint32_t done;
    asm volatile("{\n\t.reg .pred p;\n\t"
                 "mbarrier.try_wait.parity.acquire.cta.shared::cta.b64 p, [%1], %2;\n\t"
                 "selp.b32 %0, 1, 0, p;\n\t}"
                 : "=r"(done) : "r"(addr), "r"(parity) : "memory");
    while (!done) {
        asm volatile("{\n\t.reg .pred p;\n\t"
                     "mbarrier.try_wait.parity.acquire.cta.shared::cta.b64 p, [%1], %2, 0x989680;\n\t"
                     "selp.b32 %0, 1, 0, p;\n\t}"
                     : "=r"(done) : "r"(addr), "r"(parity) : "memory");
    }
}

// Persistent kernel: 148 blocks x 128 threads. Each block runs two
// independent 64-thread point-slots (warps span all 4 SMSPs). Each slot
// streams its points with a 2-stage cp.async.bulk double buffer.
__global__ __launch_bounds__(THREADS, 1)
void axon_map_kernel(const float* __restrict__ amp,
                     const float* __restrict__ pexp,
                     float* __restrict__ out) {
    extern __shared__ __align__(128) char smem_raw[];
    float* tiles = reinterpret_cast<float*>(smem_raw);                 // [SLOTS][STAGES][7680]
    float* ampt  = tiles + SMEM_TILES_FLOATS;                          // [NE][NB]
    unsigned long long* mbar =
        reinterpret_cast<unsigned long long*>(ampt + NE * NB);         // [SLOTS][STAGES]
    float* red   = reinterpret_cast<float*>(mbar + SLOTS * STAGES);    // [SLOTS][2warp][2av][NB]

    const int tid   = threadIdx.x;
    const int slot  = tid >> 6;       // 0 or 1
    const int tid64 = tid & 63;
    const int gslot = blockIdx.x * SLOTS + slot;

    // Init barriers + stage amp transposed.
    if (tid < SLOTS * STAGES) {
        const uint32_t a = (uint32_t)__cvta_generic_to_shared(&mbar[tid]);
        asm volatile("mbarrier.init.shared.b64 [%0], 1;" :: "r"(a) : "memory");
    }
    for (int i = tid; i < NB * NE; i += THREADS) {
        const int b = i / NE, e = i % NE;
        ampt[e * NB + b] = amp[i];
    }
    __syncthreads();

    float* stage_tile[STAGES];
    uint32_t stage_tile_addr[STAGES], stage_mbar_addr[STAGES];
    #pragma unroll
    for (int s = 0; s < STAGES; s++) {
        stage_tile[s] = tiles + (slot * STAGES + s) * TILE_FLOATS;
        stage_tile_addr[s] = (uint32_t)__cvta_generic_to_shared(stage_tile[s]);
        stage_mbar_addr[s] = (uint32_t)__cvta_generic_to_shared(&mbar[slot * STAGES + s]);
    }

    // Prologue: issue TMA for the first two points of this slot.
    if (tid64 == 0) {
        #pragma unroll
        for (int s = 0; s < STAGES; s++) {
            const int p = gslot + s * NSLOTS;
            if (p < NP) {
                asm volatile("mbarrier.arrive.expect_tx.shared.b64 _, [%0], %1;"
                             :: "r"(stage_mbar_addr[s]), "r"((uint32_t)TILE_BYTES) : "memory");
                asm volatile("cp.async.bulk.shared::cluster.global.mbarrier::complete_tx::bytes "
                             "[%0], [%1], %2, [%3];"
                             :: "r"(stage_tile_addr[s]),
                                "l"(pexp + (size_t)p * TILE_FLOATS),
                                "r"((uint32_t)TILE_BYTES), "r"(stage_mbar_addr[s])
                             : "memory");
            }
        }
    }

    const int warp = tid64 >> 5;      // warp within slot: 0/1
    const int lane = tid64 & 31;
    const int bar_id = slot + 1;      // named barrier per slot
    uint32_t ph[STAGES] = {0u, 0u};
    int it = 0;

    for (int p = gslot; p < NP; p += NSLOTS, it++) {
        const int st = it & 1;
        mbar_wait(stage_mbar_addr[st], ph[st]);
        ph[st] ^= 1u;

        const float* row0 = stage_tile[st] + tid64 * NE;
        const float* row1 = row0 + 64 * NE;

        unsigned long long acc0[4], acc1[4];
        #pragma unroll
        for (int q = 0; q < 4; q++) { acc0[q] = 0ull; acc1[q] = 0ull; }

        #pragma unroll
        for (int j = 0; j < NE / 4; j++) {
            const float4 r0 = *reinterpret_cast<const float4*>(row0 + 4 * j);
            const float4 r1 = *reinterpret_cast<const float4*>(row1 + 4 * j);
            const float re0[4] = {r0.x, r0.y, r0.z, r0.w};
            const float re1[4] = {r1.x, r1.y, r1.z, r1.w};
            #pragma unroll
            for (int k = 0; k < 4; k++) {
                const int e = 4 * j + k;
                const ulonglong2 alo = *reinterpret_cast<const ulonglong2*>(ampt + e * NB);
                const ulonglong2 ahi = *reinterpret_cast<const ulonglong2*>(ampt + e * NB + 4);
                const unsigned long long d0 = dup2(re0[k]);
                fma2(acc0[0], d0, alo.x);
                fma2(acc0[1], d0, alo.y);
                fma2(acc0[2], d0, ahi.x);
                fma2(acc0[3], d0, ahi.y);
                const unsigned long long d1 = dup2(re1[k]);
                fma2(acc1[0], d1, alo.x);
                fma2(acc1[1], d1, alo.y);
                fma2(acc1[2], d1, ahi.x);
                fma2(acc1[3], d1, ahi.y);
            }
        }

        // abs-argmax over 128 segments per batch (warp shuffle + cross-warp smem).
        float* red_a = red + slot * (2 * 2 * NB) + 0 * NB;   // [warp][b]
        float* red_v = red + slot * (2 * 2 * NB) + 2 * NB;
        #pragma unroll
        for (int b = 0; b < NB; b++) {
            const unsigned long long pa = acc0[b >> 1];
            const unsigned long long pb = acc1[b >> 1];
            const float v0 = __uint_as_float((b & 1) ? (uint32_t)(pa >> 32) : (uint32_t)pa);
            const float v1 = __uint_as_float((b & 1) ? (uint32_t)(pb >> 32) : (uint32_t)pb);
            float bv = v0, ba = fabsf(v0);
            const float a1f = fabsf(v1);
            if (a1f > ba) { ba = a1f; bv = v1; }
            #pragma unroll
            for (int off = 16; off > 0; off >>= 1) {
                const float oa = __shfl_xor_sync(0xffffffffu, ba, off);
                const float ov = __shfl_xor_sync(0xffffffffu, bv, off);
                if (oa > ba) { ba = oa; bv = ov; }
            }
            if (lane == 0) { red_a[warp * NB + b] = ba; red_v[warp * NB + b] = bv; }
        }
        asm volatile("bar.sync %0, %1;" :: "r"(bar_id), "r"(64) : "memory");

        if (tid64 < NB) {
            float ba = red_a[tid64];
            float bv = red_v[tid64];
            if (red_a[NB + tid64] > ba) { bv = red_v[NB + tid64]; }
            out[tid64 * NP + p] = bv;     // threshold |v|>0 is identity
        }

        // Refill this stage with point p + 2*NSLOTS (tile reads done: bar above).
        const int pn = p + STAGES * NSLOTS;
        if (tid64 == 0 && pn < NP) {
            asm volatile("mbarrier.arrive.expect_tx.shared.b64 _, [%0], %1;"
                         :: "r"(stage_mbar_addr[st]), "r"((uint32_t)TILE_BYTES) : "memory");
            asm volatile("cp.async.bulk.shared::cluster.global.mbarrier::complete_tx::bytes "
                         "[%0], [%1], %2, [%3];"
                         :: "r"(stage_tile_addr[st]),
                            "l"(pexp + (size_t)pn * TILE_FLOATS),
                            "r"((uint32_t)TILE_BYTES), "r"(stage_mbar_addr[st])
                         : "memory");
        }
    }
}

extern "C" void kernel_launch(void* const* d_in, const int* in_sizes, int n_in,
                              void* d_out, int out_size) {
    (void)n_in; (void)out_size;
    const float* a0 = (const float*)d_in[0];
    const float* a1 = (const float*)d_in[1];
    const float* amp  = a0;
    const float* pexp = a1;
    if (in_sizes[0] != NB * NE) { amp = a1; pexp = a0; }

    cudaFuncSetAttribute(axon_map_kernel,
                         cudaFuncAttributeMaxDynamicSharedMemorySize, SMEM_BYTES);
    axon_map_kernel<<<NBLOCKS, THREADS, SMEM_BYTES>>>(amp, pexp, (float*)d_out);
}